// round 10
// baseline (speedup 1.0000x reference)
#include <cuda_runtime.h>
#include <cuda_bf16.h>
#include <cstdint>

// Problem constants
#define BB 1024
#define UU 8
#define II 512
#define HH 512
#define GN 1536      // 3*H

// GEMM tiling (tf32 single-pass)
#define TM 128
#define TN 256
#define KC 32                 // fp32 k per stage (128 B rows)
#define NSTEPS (II / KC)      // 16
#define STAGES 4
#define ST_B (TM * 128)                       // A: 16 KB, then B: 32 KB
#define STAGE_BYTES (TM * 128 + TN * 128)     // 48 KB
#define SMEM_BYTES (STAGES * STAGE_BYTES)     // 192 KB

// ---------------------------------------------------------------------------
// Device scratch
// ---------------------------------------------------------------------------
// tf32-rounded copies (fp32 storage). Activations de-interleaved [U][B][K].
__device__ float g_xt [(size_t)UU * BB * II];
__device__ float g_ht [(size_t)UU * BB * II];
__device__ float g_wit[(size_t)UU * GN * II];
__device__ float g_wht[(size_t)UU * GN * II];
__device__ float g_gx [(size_t)BB * UU * GN];            // [B][U][GN]
__device__ float g_gh [(size_t)BB * UU * GN];

// ---------------------------------------------------------------------------
// helpers
// ---------------------------------------------------------------------------
__device__ __forceinline__ uint32_t smem_u32(const void* p) {
    return (uint32_t)__cvta_generic_to_shared(p);
}
__device__ __forceinline__ uint32_t sw128(uint32_t off) {
    return off ^ ((off >> 3) & 0x70);
}

#define CP_ASYNC16(dst, src) \
    asm volatile("cp.async.cg.shared.global [%0], [%1], 16;" :: "r"(dst), "l"(src))
#define CP_COMMIT() asm volatile("cp.async.commit_group;" ::: "memory")
#define CP_WAIT2()  asm volatile("cp.async.wait_group 2;" ::: "memory")

#define LDMATRIX_X4(r0, r1, r2, r3, addr) \
    asm volatile("ldmatrix.sync.aligned.m8n8.x4.shared.b16 {%0,%1,%2,%3}, [%4];" \
                 : "=r"(r0), "=r"(r1), "=r"(r2), "=r"(r3) : "r"(addr))

// round-to-nearest f32 -> tf32 bit pattern (in a b32 reg)
#define CVT_TF32_U(r) asm volatile("cvt.rna.tf32.f32 %0, %0;" : "+r"(r))

#define MMA_TF32(c, a0, a1, a2, a3, b0, b1) \
    asm volatile("mma.sync.aligned.m16n8k8.row.col.f32.tf32.tf32.f32 " \
                 "{%0,%1,%2,%3}, {%4,%5,%6,%7}, {%8,%9}, {%0,%1,%2,%3};" \
                 : "+f"((c)[0]), "+f"((c)[1]), "+f"((c)[2]), "+f"((c)[3]) \
                 : "r"(a0), "r"(a1), "r"(a2), "r"(a3), "r"(b0), "r"(b1))

// ---------------------------------------------------------------------------
// fp32 -> tf32-rounded fp32 pre-pass, 4 elems/thread.
// wmode=0 (activations): dst rows de-interleaved [B][U] -> [U][B]
// wmode=1 (weights):     dst rows unchanged
// ---------------------------------------------------------------------------
__global__ __launch_bounds__(256) void cvt_tf32_kernel(
    const uint4* __restrict__ src, uint4* __restrict__ dst,
    int total4, int wmode)
{
    const int i = blockIdx.x * blockDim.x + threadIdx.x;   // over total/4
    if (i >= total4) return;

    const int k4  = i & 127;          // 512/4 = 128 uint4 per row
    const int row = i >> 7;

    uint4 v = src[i];
    CVT_TF32_U(v.x); CVT_TF32_U(v.y); CVT_TF32_U(v.z); CVT_TF32_U(v.w);

    const int drow = wmode ? row : ((row & 7) * BB + (row >> 3));
    dst[(size_t)drow * 128 + k4] = v;
}

// ---------------------------------------------------------------------------
// tf32 mma.sync GEMM on pre-rounded data (no CVT in mainloop):
//   C[b, u, g] = sum_k A[u, b, k] * W[u, g, k]
// CTA tile 128x256, 8 warps (2M x 4N), warp tile 64x64.
// grid = (GN/TN=6, BB/TM=8, 16); z = u*2 + which
// ---------------------------------------------------------------------------
__global__ __launch_bounds__(256, 1) void gemm_tf32_kernel()
{
    extern __shared__ __align__(1024) char smem[];

    const int z = blockIdx.z;
    const int u = z >> 1;
    const int w = z & 1;
    const float* __restrict__ Asrc = w ? g_ht : g_xt;
    const float* __restrict__ Wsrc = (w ? g_wht : g_wit) + (size_t)u * GN * II;
    float* __restrict__ C = w ? g_gh : g_gx;

    const int m0 = blockIdx.y * TM;
    const int n0 = blockIdx.x * TN;

    const int tid  = threadIdx.x;
    const int wid  = tid >> 5;
    const int lane = tid & 31;
    const int wm   = wid & 1;        // warp M position (0..1)
    const int wn   = wid >> 1;       // warp N position (0..3)

    const uint32_t sb = smem_u32(smem);

    // ---------- loader precompute ----------
    // A tile: 128 rows x 128 B (32 fp32). De-interleaved: row b at (u*BB+b)*II.
    uint32_t a_off[4];  const float* a_src[4];
    #pragma unroll
    for (int j = 0; j < 4; ++j) {
        const int idx = tid + 256 * j;          // 0..1023
        const int r = idx >> 3, v = idx & 7;
        a_off[j] = sw128((uint32_t)(r * 128 + v * 16));
        a_src[j] = Asrc + ((size_t)u * BB + m0 + r) * II + v * 4;
    }
    // B tile: 256 rows x 128 B. Row g at g*II (contiguous).
    uint32_t b_off[8];  const float* b_src[8];
    #pragma unroll
    for (int j = 0; j < 8; ++j) {
        const int idx = tid + 256 * j;          // 0..2047
        const int r = idx >> 3, v = idx & 7;
        b_off[j] = sw128((uint32_t)(r * 128 + v * 16));
        b_src[j] = Wsrc + (size_t)(n0 + r) * II + v * 4;
    }

    // ---------- fragment address precompute (tf32 via b16 ldmatrix) ----------
    const uint32_t a_row  = (uint32_t)((lane & 7) + ((lane >> 3) & 1) * 8);
    const uint32_t a_colB = (uint32_t)((lane >> 4) << 4);
    uint32_t a_frag_off[4];
    #pragma unroll
    for (int mt = 0; mt < 4; ++mt)
        a_frag_off[mt] = (uint32_t)((wm * 64 + mt * 16 + a_row) * 128) + a_colB;

    const uint32_t b_row  = (uint32_t)((lane & 7) + ((lane >> 4) & 1) * 8);
    const uint32_t b_colB = (uint32_t)(((lane >> 3) & 1) << 4);
    uint32_t b_frag_off[4];
    #pragma unroll
    for (int nb = 0; nb < 4; ++nb)
        b_frag_off[nb] = (uint32_t)((wn * 64 + nb * 16 + b_row) * 128) + b_colB;

    float acc[4][8][4];
    #pragma unroll
    for (int mt = 0; mt < 4; ++mt)
        #pragma unroll
        for (int nt = 0; nt < 8; ++nt)
            #pragma unroll
            for (int q = 0; q < 4; ++q) acc[mt][nt][q] = 0.0f;

    // ---------- stage load ----------
    auto load_stage = [&](int st) {
        const uint32_t abase = sb + (uint32_t)st * STAGE_BYTES;
        const uint32_t bbase = abase + ST_B;
        #pragma unroll
        for (int j = 0; j < 4; ++j) {
            CP_ASYNC16(abase + a_off[j], a_src[j]);
            a_src[j] += KC;
        }
        #pragma unroll
        for (int j = 0; j < 8; ++j) {
            CP_ASYNC16(bbase + b_off[j], b_src[j]);
            b_src[j] += KC;
        }
    };

    // prologue: stages 0..2
    #pragma unroll
    for (int p = 0; p < STAGES - 1; ++p) { load_stage(p); CP_COMMIT(); }

    for (int s = 0; s < NSTEPS; ++s) {
        CP_WAIT2();              // stage s ready
        __syncthreads();         // all warps done with stage s-1 -> safe to refill

        if (s + STAGES - 1 < NSTEPS) load_stage((s + STAGES - 1) & (STAGES - 1));
        CP_COMMIT();             // commit every iter to keep group counts aligned

        const uint32_t As = sb + (uint32_t)(s & (STAGES - 1)) * STAGE_BYTES;
        const uint32_t Bs = As + ST_B;

        #pragma unroll
        for (int kk = 0; kk < 4; ++kk) {        // 4 x k8 within KC=32
            uint32_t a[4][4], b[4][4];
            #pragma unroll
            for (int mt = 0; mt < 4; ++mt) {
                const uint32_t addr = As + sw128(a_frag_off[mt] + kk * 32);
                LDMATRIX_X4(a[mt][0], a[mt][1], a[mt][2], a[mt][3], addr);
            }
            #pragma unroll
            for (int nb = 0; nb < 4; ++nb) {
                const uint32_t addr = Bs + sw128(b_frag_off[nb] + kk * 32);
                LDMATRIX_X4(b[nb][0], b[nb][1], b[nb][2], b[nb][3], addr);
            }
            #pragma unroll
            for (int mt = 0; mt < 4; ++mt) {
                #pragma unroll
                for (int nb = 0; nb < 4; ++nb) {
                    MMA_TF32(acc[mt][2 * nb],
                             a[mt][0], a[mt][1], a[mt][2], a[mt][3],
                             b[nb][0], b[nb][1]);
                    MMA_TF32(acc[mt][2 * nb + 1],
                             a[mt][0], a[mt][1], a[mt][2], a[mt][3],
                             b[nb][2], b[nb][3]);
                }
            }
        }
    }

    // ---------- epilogue: regs -> global ([B][U][GN]) ----------
    const int g = lane >> 2;         // 0..7
    const int d = lane & 3;          // 0..3
    #pragma unroll
    for (int mt = 0; mt < 4; ++mt) {
        const int row0 = m0 + wm * 64 + mt * 16 + g;
        float* __restrict__ c0 = C + ((size_t)row0 * UU + u) * GN;
        float* __restrict__ c1 = C + ((size_t)(row0 + 8) * UU + u) * GN;
        #pragma unroll
        for (int nt = 0; nt < 8; ++nt) {
            const int col = n0 + wn * 64 + nt * 8 + d * 2;
            float2 v0 = {acc[mt][nt][0], acc[mt][nt][1]};
            float2 v1 = {acc[mt][nt][2], acc[mt][nt][3]};
            *reinterpret_cast<float2*>(c0 + col) = v0;
            *reinterpret_cast<float2*>(c1 + col) = v1;
        }
    }
}

// ---------------------------------------------------------------------------
// Elementwise GRU gates (+bias fold), 4 outputs/thread (float4)
// ---------------------------------------------------------------------------
__global__ __launch_bounds__(256) void gru_elem_kernel(
    const float4* __restrict__ Hi,    // hidden [B][U][H] as float4
    const float* __restrict__ bih,
    const float* __restrict__ bhh,
    float4* __restrict__ out)
{
    const int i = blockIdx.x * blockDim.x + threadIdx.x;   // over B*U*H/4
    if (i >= BB * UU * HH / 4) return;

    const int j4 = i & 127;          // H/4 = 128
    const int bu = i >> 7;
    const int u  = bu & (UU - 1);

    const float4* __restrict__ gx = reinterpret_cast<const float4*>(g_gx + (size_t)bu * GN) + j4;
    const float4* __restrict__ gh = reinterpret_cast<const float4*>(g_gh + (size_t)bu * GN) + j4;
    const float4* __restrict__ bi = reinterpret_cast<const float4*>(bih + u * GN) + j4;
    const float4* __restrict__ bh = reinterpret_cast<const float4*>(bhh + u * GN) + j4;

    const float4 xr = gx[0],   hr = gh[0];
    const float4 xz = gx[128], hz = gh[128];
    const float4 xn = gx[256], hn = gh[256];
    const float4 br = bi[0],   cr = bh[0];
    const float4 bz = bi[128], cz = bh[128];
    const float4 bn = bi[256], cn = bh[256];
    const float4 h  = Hi[i];

    float4 o;
    {
        const float r = 1.0f / (1.0f + __expf(-(xr.x + br.x + hr.x + cr.x)));
        const float zz = 1.0f / (1.0f + __expf(-(xz.x + bz.x + hz.x + cz.x)));
        const float n = tanhf(xn.x + bn.x + r * (hn.x + cn.x));
        o.x = (1.0f - zz) * n + zz * h.x;
    }
    {
        const float r = 1.0f / (1.0f + __expf(-(xr.y + br.y + hr.y + cr.y)));
        const float zz = 1.0f / (1.0f + __expf(-(xz.y + bz.y + hz.y + cz.y)));
        const float n = tanhf(xn.y + bn.y + r * (hn.y + cn.y));
        o.y = (1.0f - zz) * n + zz * h.y;
    }
    {
        const float r = 1.0f / (1.0f + __expf(-(xr.z + br.z + hr.z + cr.z)));
        const float zz = 1.0f / (1.0f + __expf(-(xz.z + bz.z + hz.z + cz.z)));
        const float n = tanhf(xn.z + bn.z + r * (hn.z + cn.z));
        o.z = (1.0f - zz) * n + zz * h.z;
    }
    {
        const float r = 1.0f / (1.0f + __expf(-(xr.w + br.w + hr.w + cr.w)));
        const float zz = 1.0f / (1.0f + __expf(-(xz.w + bz.w + hz.w + cz.w)));
        const float n = tanhf(xn.w + bn.w + r * (hn.w + cn.w));
        o.w = (1.0f - zz) * n + zz * h.w;
    }
    out[i] = o;
}

// ---------------------------------------------------------------------------
extern "C" void kernel_launch(void* const* d_in, const int* in_sizes, int n_in,
                              void* d_out, int out_size)
{
    const float* inputs = (const float*)d_in[0];  // [B,U,I]
    const float* hidden = (const float*)d_in[1];  // [B,U,H]
    const float* W_ih   = (const float*)d_in[2];  // [U,3H,I]
    const float* W_hh   = (const float*)d_in[3];  // [U,3H,H]
    const float* b_ih   = (const float*)d_in[4];  // [U,3H]
    const float* b_hh   = (const float*)d_in[5];  // [U,3H]
    float* out = (float*)d_out;                   // [B,U,H]

    cudaFuncSetAttribute(gemm_tf32_kernel,
                         cudaFuncAttributeMaxDynamicSharedMemorySize, SMEM_BYTES);

    float *xt, *ht, *wit, *wht;
    cudaGetSymbolAddress((void**)&xt,  g_xt);
    cudaGetSymbolAddress((void**)&ht,  g_ht);
    cudaGetSymbolAddress((void**)&wit, g_wit);
    cudaGetSymbolAddress((void**)&wht, g_wht);

    const int act4 = BB * UU * II / 4;      // 1,048,576
    const int w4   = UU * GN * II / 4;      // 1,572,864
    cvt_tf32_kernel<<<(act4 + 255) / 256, 256>>>((const uint4*)inputs, (uint4*)xt,  act4, 0);
    cvt_tf32_kernel<<<(act4 + 255) / 256, 256>>>((const uint4*)hidden, (uint4*)ht,  act4, 0);
    cvt_tf32_kernel<<<(w4   + 255) / 256, 256>>>((const uint4*)W_ih,   (uint4*)wit, w4,   1);
    cvt_tf32_kernel<<<(w4   + 255) / 256, 256>>>((const uint4*)W_hh,   (uint4*)wht, w4,   1);

    dim3 gemm_grid(GN / TN, BB / TM, UU * 2);   // (6, 8, 16)
    gemm_tf32_kernel<<<gemm_grid, 256, SMEM_BYTES>>>();

    const int total4 = BB * UU * HH / 4;
    gru_elem_kernel<<<(total4 + 255) / 256, 256>>>(
        (const float4*)hidden, b_ih, b_hh, (float4*)out);
}

// round 11
// speedup vs baseline: 1.4774x; 1.4774x over previous
#include <cuda_runtime.h>
#include <cuda_fp16.h>
#include <cstdint>

// Problem constants
#define BB 1024
#define UU 8
#define II 512
#define HH 512
#define GN 1536      // 3*H

// GEMM tiling (fp16 single-pass, m16n8k16)
#define TM 128
#define TN 256
#define KC 64                 // fp16 k per stage (128 B rows)
#define NSTEPS (II / KC)      // 8
#define STAGES 4
#define ST_B (TM * 128)                       // A: 16 KB, then B: 32 KB
#define STAGE_BYTES (TM * 128 + TN * 128)     // 48 KB
#define SMEM_BYTES (STAGES * STAGE_BYTES)     // 192 KB

// ---------------------------------------------------------------------------
// Device scratch
// ---------------------------------------------------------------------------
// fp16 copies. Activations de-interleaved [U][B][K]; weights [U][GN][K].
__device__ __half g_xh [(size_t)UU * BB * II];
__device__ __half g_hh [(size_t)UU * BB * II];
__device__ __half g_wih[(size_t)UU * GN * II];
__device__ __half g_whh[(size_t)UU * GN * II];
__device__ float g_gx [(size_t)BB * UU * GN];            // [B][U][GN]
__device__ float g_gh [(size_t)BB * UU * GN];

// ---------------------------------------------------------------------------
// helpers
// ---------------------------------------------------------------------------
__device__ __forceinline__ uint32_t smem_u32(const void* p) {
    return (uint32_t)__cvta_generic_to_shared(p);
}
__device__ __forceinline__ uint32_t sw128(uint32_t off) {
    return off ^ ((off >> 3) & 0x70);
}

#define CP_ASYNC16(dst, src) \
    asm volatile("cp.async.cg.shared.global [%0], [%1], 16;" :: "r"(dst), "l"(src))
#define CP_COMMIT() asm volatile("cp.async.commit_group;" ::: "memory")
#define CP_WAIT2()  asm volatile("cp.async.wait_group 2;" ::: "memory")

#define LDMATRIX_X4(r0, r1, r2, r3, addr) \
    asm volatile("ldmatrix.sync.aligned.m8n8.x4.shared.b16 {%0,%1,%2,%3}, [%4];" \
                 : "=r"(r0), "=r"(r1), "=r"(r2), "=r"(r3) : "r"(addr))

#define MMA_16816_F16(c, a, b0, b1) \
    asm volatile("mma.sync.aligned.m16n8k16.row.col.f32.f16.f16.f32 " \
                 "{%0,%1,%2,%3}, {%4,%5,%6,%7}, {%8,%9}, {%0,%1,%2,%3};" \
                 : "+f"((c)[0]), "+f"((c)[1]), "+f"((c)[2]), "+f"((c)[3]) \
                 : "r"((a)[0]), "r"((a)[1]), "r"((a)[2]), "r"((a)[3]), \
                   "r"(b0), "r"(b1))

// ---------------------------------------------------------------------------
// fp32 -> fp16 conversion, 4 elems/thread (float4 -> 4 halves).
// wmode=0 (activations): dst rows de-interleaved [B][U] -> [U][B]
// wmode=1 (weights):     dst rows unchanged
// ---------------------------------------------------------------------------
__global__ __launch_bounds__(256) void cvt_half_kernel(
    const float4* __restrict__ src, __half* __restrict__ dst,
    int total4, int wmode)
{
    const int i = blockIdx.x * blockDim.x + threadIdx.x;   // over total/4
    if (i >= total4) return;

    const int k4  = i & 127;          // 512/4 = 128 float4 per row
    const int row = i >> 7;

    const float4 v = src[i];
    __half2 p01 = __floats2half2_rn(v.x, v.y);
    __half2 p23 = __floats2half2_rn(v.z, v.w);
    uint2 pack;
    pack.x = *reinterpret_cast<uint32_t*>(&p01);
    pack.y = *reinterpret_cast<uint32_t*>(&p23);

    const int drow = wmode ? row : ((row & 7) * BB + (row >> 3));
    reinterpret_cast<uint2*>(dst + (size_t)drow * II)[k4] = pack;
}

// ---------------------------------------------------------------------------
// fp16 mma.sync GEMM: C[b, u, g] = sum_k A[u, b, k] * W[u, g, k]
// CTA tile 128x256, 8 warps (2M x 4N), warp tile 64x64.
// grid = (GN/TN=6, BB/TM=8, 16); z = u*2 + which
// ---------------------------------------------------------------------------
__global__ __launch_bounds__(256, 1) void gemm_f16_kernel()
{
    extern __shared__ __align__(1024) char smem[];

    const int z = blockIdx.z;
    const int u = z >> 1;
    const int w = z & 1;
    const __half* __restrict__ Asrc = w ? g_hh : g_xh;
    const __half* __restrict__ Wsrc = (w ? g_whh : g_wih) + (size_t)u * GN * II;
    float* __restrict__ C = w ? g_gh : g_gx;

    const int m0 = blockIdx.y * TM;
    const int n0 = blockIdx.x * TN;

    const int tid  = threadIdx.x;
    const int wid  = tid >> 5;
    const int lane = tid & 31;
    const int wm   = wid & 1;        // warp M position (0..1)
    const int wn   = wid >> 1;       // warp N position (0..3)

    const uint32_t sb = smem_u32(smem);

    // ---------- loader precompute ----------
    // A tile: 128 rows x 128 B (64 fp16). Row b at (u*BB+b)*II.
    uint32_t a_off[4];  const __half* a_src[4];
    #pragma unroll
    for (int j = 0; j < 4; ++j) {
        const int idx = tid + 256 * j;          // 0..1023
        const int r = idx >> 3, v = idx & 7;
        a_off[j] = sw128((uint32_t)(r * 128 + v * 16));
        a_src[j] = Asrc + ((size_t)u * BB + m0 + r) * II + v * 8;
    }
    // B tile: 256 rows x 128 B. Row g at g*II (contiguous).
    uint32_t b_off[8];  const __half* b_src[8];
    #pragma unroll
    for (int j = 0; j < 8; ++j) {
        const int idx = tid + 256 * j;          // 0..2047
        const int r = idx >> 3, v = idx & 7;
        b_off[j] = sw128((uint32_t)(r * 128 + v * 16));
        b_src[j] = Wsrc + (size_t)(n0 + r) * II + v * 8;
    }

    // ---------- fragment address precompute (b16 k-major, proven in R6) ----------
    const uint32_t a_row  = (uint32_t)(lane & 15);
    const uint32_t a_colB = (uint32_t)((lane >> 4) << 4);
    uint32_t a_frag_off[4];
    #pragma unroll
    for (int mt = 0; mt < 4; ++mt)
        a_frag_off[mt] = (uint32_t)((wm * 64 + mt * 16 + a_row) * 128) + a_colB;

    const uint32_t b_row  = (uint32_t)((lane & 7) | ((lane >> 4) << 3));
    const uint32_t b_colB = (uint32_t)(((lane >> 3) & 1) << 4);
    uint32_t b_frag_off[4];
    #pragma unroll
    for (int nb = 0; nb < 4; ++nb)
        b_frag_off[nb] = (uint32_t)((wn * 64 + nb * 16 + b_row) * 128) + b_colB;

    float acc[4][8][4];
    #pragma unroll
    for (int mt = 0; mt < 4; ++mt)
        #pragma unroll
        for (int nt = 0; nt < 8; ++nt)
            #pragma unroll
            for (int q = 0; q < 4; ++q) acc[mt][nt][q] = 0.0f;

    // ---------- stage load ----------
    auto load_stage = [&](int st) {
        const uint32_t abase = sb + (uint32_t)st * STAGE_BYTES;
        const uint32_t bbase = abase + ST_B;
        #pragma unroll
        for (int j = 0; j < 4; ++j) {
            CP_ASYNC16(abase + a_off[j], a_src[j]);
            a_src[j] += KC;
        }
        #pragma unroll
        for (int j = 0; j < 8; ++j) {
            CP_ASYNC16(bbase + b_off[j], b_src[j]);
            b_src[j] += KC;
        }
    };

    // prologue: stages 0..2
    #pragma unroll
    for (int p = 0; p < STAGES - 1; ++p) { load_stage(p); CP_COMMIT(); }

    for (int s = 0; s < NSTEPS; ++s) {
        CP_WAIT2();              // stage s ready
        __syncthreads();         // all warps done with stage s-1 -> safe to refill

        if (s + STAGES - 1 < NSTEPS) load_stage((s + STAGES - 1) & (STAGES - 1));
        CP_COMMIT();             // keep group counts aligned

        const uint32_t As = sb + (uint32_t)(s & (STAGES - 1)) * STAGE_BYTES;
        const uint32_t Bs = As + ST_B;

        #pragma unroll
        for (int kk = 0; kk < 4; ++kk) {        // 4 x k16 within KC=64
            uint32_t a[4][4], b[4][4];
            #pragma unroll
            for (int mt = 0; mt < 4; ++mt) {
                const uint32_t addr = As + sw128(a_frag_off[mt] + kk * 32);
                LDMATRIX_X4(a[mt][0], a[mt][1], a[mt][2], a[mt][3], addr);
            }
            #pragma unroll
            for (int nb = 0; nb < 4; ++nb) {
                const uint32_t addr = Bs + sw128(b_frag_off[nb] + kk * 32);
                LDMATRIX_X4(b[nb][0], b[nb][1], b[nb][2], b[nb][3], addr);
            }
            #pragma unroll
            for (int mt = 0; mt < 4; ++mt) {
                #pragma unroll
                for (int nb = 0; nb < 4; ++nb) {
                    MMA_16816_F16(acc[mt][2 * nb],     a[mt], b[nb][0], b[nb][1]);
                    MMA_16816_F16(acc[mt][2 * nb + 1], a[mt], b[nb][2], b[nb][3]);
                }
            }
        }
    }

    // ---------- epilogue: regs -> global ([B][U][GN]) ----------
    const int g = lane >> 2;         // 0..7
    const int d = lane & 3;          // 0..3
    #pragma unroll
    for (int mt = 0; mt < 4; ++mt) {
        const int row0 = m0 + wm * 64 + mt * 16 + g;
        float* __restrict__ c0 = C + ((size_t)row0 * UU + u) * GN;
        float* __restrict__ c1 = C + ((size_t)(row0 + 8) * UU + u) * GN;
        #pragma unroll
        for (int nt = 0; nt < 8; ++nt) {
            const int col = n0 + wn * 64 + nt * 8 + d * 2;
            float2 v0 = {acc[mt][nt][0], acc[mt][nt][1]};
            float2 v1 = {acc[mt][nt][2], acc[mt][nt][3]};
            *reinterpret_cast<float2*>(c0 + col) = v0;
            *reinterpret_cast<float2*>(c1 + col) = v1;
        }
    }
}

// ---------------------------------------------------------------------------
// Elementwise GRU gates (+bias fold), 4 outputs/thread (float4)
// ---------------------------------------------------------------------------
__global__ __launch_bounds__(256) void gru_elem_kernel(
    const float4* __restrict__ Hi,    // hidden [B][U][H] as float4
    const float* __restrict__ bih,
    const float* __restrict__ bhh,
    float4* __restrict__ out)
{
    const int i = blockIdx.x * blockDim.x + threadIdx.x;   // over B*U*H/4
    if (i >= BB * UU * HH / 4) return;

    const int j4 = i & 127;          // H/4 = 128
    const int bu = i >> 7;
    const int u  = bu & (UU - 1);

    const float4* __restrict__ gx = reinterpret_cast<const float4*>(g_gx + (size_t)bu * GN) + j4;
    const float4* __restrict__ gh = reinterpret_cast<const float4*>(g_gh + (size_t)bu * GN) + j4;
    const float4* __restrict__ bi = reinterpret_cast<const float4*>(bih + u * GN) + j4;
    const float4* __restrict__ bh = reinterpret_cast<const float4*>(bhh + u * GN) + j4;

    const float4 xr = gx[0],   hr = gh[0];
    const float4 xz = gx[128], hz = gh[128];
    const float4 xn = gx[256], hn = gh[256];
    const float4 br = bi[0],   cr = bh[0];
    const float4 bz = bi[128], cz = bh[128];
    const float4 bn = bi[256], cn = bh[256];
    const float4 h  = Hi[i];

    float4 o;
    {
        const float r = 1.0f / (1.0f + __expf(-(xr.x + br.x + hr.x + cr.x)));
        const float zz = 1.0f / (1.0f + __expf(-(xz.x + bz.x + hz.x + cz.x)));
        const float n = tanhf(xn.x + bn.x + r * (hn.x + cn.x));
        o.x = (1.0f - zz) * n + zz * h.x;
    }
    {
        const float r = 1.0f / (1.0f + __expf(-(xr.y + br.y + hr.y + cr.y)));
        const float zz = 1.0f / (1.0f + __expf(-(xz.y + bz.y + hz.y + cz.y)));
        const float n = tanhf(xn.y + bn.y + r * (hn.y + cn.y));
        o.y = (1.0f - zz) * n + zz * h.y;
    }
    {
        const float r = 1.0f / (1.0f + __expf(-(xr.z + br.z + hr.z + cr.z)));
        const float zz = 1.0f / (1.0f + __expf(-(xz.z + bz.z + hz.z + cz.z)));
        const float n = tanhf(xn.z + bn.z + r * (hn.z + cn.z));
        o.z = (1.0f - zz) * n + zz * h.z;
    }
    {
        const float r = 1.0f / (1.0f + __expf(-(xr.w + br.w + hr.w + cr.w)));
        const float zz = 1.0f / (1.0f + __expf(-(xz.w + bz.w + hz.w + cz.w)));
        const float n = tanhf(xn.w + bn.w + r * (hn.w + cn.w));
        o.w = (1.0f - zz) * n + zz * h.w;
    }
    out[i] = o;
}

// ---------------------------------------------------------------------------
extern "C" void kernel_launch(void* const* d_in, const int* in_sizes, int n_in,
                              void* d_out, int out_size)
{
    const float* inputs = (const float*)d_in[0];  // [B,U,I]
    const float* hidden = (const float*)d_in[1];  // [B,U,H]
    const float* W_ih   = (const float*)d_in[2];  // [U,3H,I]
    const float* W_hh   = (const float*)d_in[3];  // [U,3H,H]
    const float* b_ih   = (const float*)d_in[4];  // [U,3H]
    const float* b_hh   = (const float*)d_in[5];  // [U,3H]
    float* out = (float*)d_out;                   // [B,U,H]

    cudaFuncSetAttribute(gemm_f16_kernel,
                         cudaFuncAttributeMaxDynamicSharedMemorySize, SMEM_BYTES);

    __half *xh, *hh, *wih, *whh;
    cudaGetSymbolAddress((void**)&xh,  g_xh);
    cudaGetSymbolAddress((void**)&hh,  g_hh);
    cudaGetSymbolAddress((void**)&wih, g_wih);
    cudaGetSymbolAddress((void**)&whh, g_whh);

    const int act4 = BB * UU * II / 4;      // 1,048,576
    const int w4   = UU * GN * II / 4;      // 1,572,864
    cvt_half_kernel<<<(act4 + 255) / 256, 256>>>((const float4*)inputs, xh,  act4, 0);
    cvt_half_kernel<<<(act4 + 255) / 256, 256>>>((const float4*)hidden, hh,  act4, 0);
    cvt_half_kernel<<<(w4   + 255) / 256, 256>>>((const float4*)W_ih,   wih, w4,   1);
    cvt_half_kernel<<<(w4   + 255) / 256, 256>>>((const float4*)W_hh,   whh, w4,   1);

    dim3 gemm_grid(GN / TN, BB / TM, UU * 2);   // (6, 8, 16)
    gemm_f16_kernel<<<gemm_grid, 256, SMEM_BYTES>>>();

    const int total4 = BB * UU * HH / 4;
    gru_elem_kernel<<<(total4 + 255) / 256, 256>>>(
        (const float4*)hidden, b_ih, b_hh, (float4*)out);
}